// round 15
// baseline (speedup 1.0000x reference)
#include <cuda_runtime.h>
#include <cuda_bf16.h>
#include <math.h>
#include <stdint.h>

#define BATCH 4096
#define DIM   256
#define NPAIR 6
#define INV_T 10.0f
#define NCTA  (32 * 32 * NPAIR)    // pair_mma grid size

__constant__ int c_pi[NPAIR] = {0, 0, 0, 1, 1, 2};
__constant__ int c_pj[NPAIR] = {1, 2, 3, 2, 3, 3};

// Scratch (allocs forbidden)
__device__ __nv_bfloat16 g_znb[4 * BATCH * DIM];   // normalized views, bf16
__device__ float g_rowsum[NPAIR * BATCH];
__device__ float g_colsum[NPAIR * BATCH];
__device__ float g_diag[NPAIR * BATCH];
__device__ unsigned int g_ctr;                      // last-block counter

// ---------------------------------------------------------------------------
__device__ __forceinline__ uint32_t smem_u32(const void* p) {
    uint32_t a;
    asm("{ .reg .u64 t; cvta.to.shared.u64 t, %1; cvt.u32.u64 %0, t; }"
        : "=r"(a) : "l"(p));
    return a;
}

#define CP_ASYNC16(smem, gptr) \
    asm volatile("cp.async.cg.shared.global [%0], [%1], 16;" \
                 :: "r"(smem), "l"(gptr) : "memory")
#define CP_COMMIT() asm volatile("cp.async.commit_group;" ::: "memory")
#define CP_WAIT(n)  asm volatile("cp.async.wait_group %0;" :: "n"(n) : "memory")

#define LDMATRIX_X4(r0, r1, r2, r3, addr) \
    asm volatile("ldmatrix.sync.aligned.m8n8.x4.shared.b16 {%0,%1,%2,%3}, [%4];" \
                 : "=r"(r0), "=r"(r1), "=r"(r2), "=r"(r3) : "r"(addr))

#define MMA_BF16(c, a, b) \
    asm volatile("mma.sync.aligned.m16n8k16.row.col.f32.bf16.bf16.f32 " \
                 "{%0,%1,%2,%3}, {%4,%5,%6,%7}, {%8,%9}, {%0,%1,%2,%3};" \
                 : "+f"((c)[0]), "+f"((c)[1]), "+f"((c)[2]), "+f"((c)[3]) \
                 : "r"((a)[0]), "r"((a)[1]), "r"((a)[2]), "r"((a)[3]), \
                   "r"((b)[0]), "r"((b)[1]))

// ---------------------------------------------------------------------------
// Kernel 1: zero accumulators + counter (fused) + L2-normalize -> bf16.
// Two rows per warp (MLP 4).
// ---------------------------------------------------------------------------
__global__ void normalize_kernel(const float* __restrict__ z0,
                                 const float* __restrict__ z1,
                                 const float* __restrict__ z2,
                                 const float* __restrict__ z3,
                                 float* __restrict__ out) {
    int gidx = blockIdx.x * blockDim.x + threadIdx.x;
    if (gidx < NPAIR * BATCH) {
        g_rowsum[gidx] = 0.0f;
        g_colsum[gidx] = 0.0f;
    }
    if (gidx == 0) { out[0] = 0.0f; g_ctr = 0u; }

    int gwarp = gidx >> 5;                 // 0 .. 2*BATCH-1
    int lane  = threadIdx.x & 31;
    if (gwarp >= 2 * BATCH) return;

    float4 v[2][2];
    float  ss[2];
    const float* srcs[2];
#pragma unroll
    for (int r = 0; r < 2; r++) {
        int fr   = gwarp * 2 + r;          // flat row 0..16383
        int view = fr >> 12;
        int row  = fr & (BATCH - 1);
        const float* src;
        switch (view) {
            case 0: src = z0; break;
            case 1: src = z1; break;
            case 2: src = z2; break;
            default: src = z3; break;
        }
        srcs[r] = src + (size_t)row * DIM;
    }
#pragma unroll
    for (int r = 0; r < 2; r++) {
        const float4* s4 = (const float4*)srcs[r];
        v[r][0] = s4[lane * 2 + 0];
        v[r][1] = s4[lane * 2 + 1];
    }
#pragma unroll
    for (int r = 0; r < 2; r++) {
        float4 a = v[r][0], b = v[r][1];
        ss[r] = a.x * a.x + a.y * a.y + a.z * a.z + a.w * a.w
              + b.x * b.x + b.y * b.y + b.z * b.z + b.w * b.w;
    }
#pragma unroll
    for (int o = 16; o > 0; o >>= 1) {
        ss[0] += __shfl_xor_sync(0xFFFFFFFFu, ss[0], o);
        ss[1] += __shfl_xor_sync(0xFFFFFFFFu, ss[1], o);
    }
#pragma unroll
    for (int r = 0; r < 2; r++) {
        float inv = 1.0f / fmaxf(sqrtf(ss[r]), 1e-8f);
        float4 a = v[r][0], b = v[r][1];
        __nv_bfloat162 p0 = __floats2bfloat162_rn(a.x * inv, a.y * inv);
        __nv_bfloat162 p1 = __floats2bfloat162_rn(a.z * inv, a.w * inv);
        __nv_bfloat162 p2 = __floats2bfloat162_rn(b.x * inv, b.y * inv);
        __nv_bfloat162 p3 = __floats2bfloat162_rn(b.z * inv, b.w * inv);
        uint4 o4;
        o4.x = reinterpret_cast<uint32_t&>(p0);
        o4.y = reinterpret_cast<uint32_t&>(p1);
        o4.z = reinterpret_cast<uint32_t&>(p2);
        o4.w = reinterpret_cast<uint32_t&>(p3);
        int fr = gwarp * 2 + r;
        uint4* dst = (uint4*)(g_znb + (size_t)fr * DIM);
        dst[lane] = o4;
    }
}

// ---------------------------------------------------------------------------
// Kernel 2: R6-winner bf16 mma.sync pair GEMM + fused last-block finalize.
// CTA tile 128x128, 8 warps 4x2, warp tile 32x64. K chunks of 64, 3-stage
// cp.async pipeline, one barrier per chunk.
// SMEM chunk layout (128x64 bf16, 16 KB):
//   element (row, k): byte = row*128 + ((k/8) ^ (row&7))*16 + (k%8)*2
// ---------------------------------------------------------------------------
#define KC 64
#define CHUNK_BYTES (128 * 128)     // 16 KB
#define NSTAGE 3
#define SMEM_TOTAL (2 * NSTAGE * CHUNK_BYTES)   // 96 KB

__device__ __forceinline__ void load_chunk(uint32_t s_base,
                                           const __nv_bfloat16* __restrict__ src,
                                           int kc, int tid) {
#pragma unroll
    for (int it = 0; it < 4; it++) {
        int idx = it * 256 + tid;         // 0..1023
        int row = idx >> 3;
        int c   = idx & 7;
        const __nv_bfloat16* g = src + (size_t)row * DIM + kc * KC + c * 8;
        uint32_t s = s_base + row * 128 + ((c ^ (row & 7)) << 4);
        CP_ASYNC16(s, g);
    }
}

__global__ void __launch_bounds__(256) pair_mma_kernel(float* __restrict__ out) {
    extern __shared__ char smraw[];
    uint32_t sbase = smem_u32(smraw);

    int tid = threadIdx.x;
    int w = tid >> 5, lane = tid & 31;
    int warp_m = w & 3;                 // 0..3 -> 32 rows each
    int warp_n = w >> 2;                // 0..1 -> 64 cols each

    int p = blockIdx.z;
    int rowBase = blockIdx.y * 128;
    int colBase = blockIdx.x * 128;
    const __nv_bfloat16* Asrc = g_znb + ((size_t)c_pi[p] * BATCH + rowBase) * DIM;
    const __nv_bfloat16* Bsrc = g_znb + ((size_t)c_pj[p] * BATCH + colBase) * DIM;

    uint32_t sA[NSTAGE], sB[NSTAGE];
#pragma unroll
    for (int s = 0; s < NSTAGE; s++) {
        sA[s] = sbase + s * CHUNK_BYTES;
        sB[s] = sbase + (NSTAGE + s) * CHUNK_BYTES;
    }

    float c[2][8][4];
#pragma unroll
    for (int i = 0; i < 2; i++)
#pragma unroll
        for (int j = 0; j < 8; j++)
#pragma unroll
            for (int q = 0; q < 4; q++) c[i][j][q] = 0.0f;

    int ar = warp_m * 32 + (lane & 15);
    int akg = lane >> 4;
    int bn = warp_n * 64 + ((lane >> 4) << 3) + (lane & 7);
    int bkg = (lane >> 3) & 1;

    load_chunk(sA[0], Asrc, 0, tid);
    load_chunk(sB[0], Bsrc, 0, tid);
    CP_COMMIT();
    load_chunk(sA[1], Asrc, 1, tid);
    load_chunk(sB[1], Bsrc, 1, tid);
    CP_COMMIT();

#pragma unroll
    for (int kc = 0; kc < 4; kc++) {
        if (kc < 3) { CP_WAIT(1); } else { CP_WAIT(0); }
        __syncthreads();
        if (kc < 2) {
            int nb = (kc + 2) % NSTAGE;
            load_chunk(sA[nb], Asrc, kc + 2, tid);
            load_chunk(sB[nb], Bsrc, kc + 2, tid);
            CP_COMMIT();
        }
        int buf = kc % NSTAGE;

#pragma unroll
        for (int kk = 0; kk < 4; kk++) {
            uint32_t a[2][4];
#pragma unroll
            for (int fm = 0; fm < 2; fm++) {
                int r = ar + fm * 16;
                int kg = kk * 2 + akg;
                uint32_t addr = sA[buf] + r * 128 + ((kg ^ (r & 7)) << 4);
                LDMATRIX_X4(a[fm][0], a[fm][1], a[fm][2], a[fm][3], addr);
            }
            uint32_t b[4][4];
#pragma unroll
            for (int nb = 0; nb < 4; nb++) {
                int n = bn + nb * 16;
                int kg = kk * 2 + bkg;
                uint32_t addr = sB[buf] + n * 128 + ((kg ^ (n & 7)) << 4);
                LDMATRIX_X4(b[nb][0], b[nb][1], b[nb][2], b[nb][3], addr);
            }
#pragma unroll
            for (int fm = 0; fm < 2; fm++)
#pragma unroll
                for (int nb = 0; nb < 4; nb++) {
                    uint32_t bf0[2] = {b[nb][0], b[nb][1]};
                    uint32_t bf1[2] = {b[nb][2], b[nb][3]};
                    MMA_BF16(c[fm][nb * 2 + 0], a[fm], bf0);
                    MMA_BF16(c[fm][nb * 2 + 1], a[fm], bf1);
                }
        }
    }

    // ------------------- epilogue (register-only, proven R6 form) ----------
    bool diag_cta = (rowBase == colBase);
    float rsum[2][2] = {{0, 0}, {0, 0}};
    float csum[16];
#pragma unroll
    for (int i = 0; i < 16; i++) csum[i] = 0.0f;

#pragma unroll
    for (int fm = 0; fm < 2; fm++)
#pragma unroll
        for (int fn = 0; fn < 8; fn++)
#pragma unroll
            for (int q = 0; q < 4; q++) {
                int i = q >> 1, j = q & 1;
                float s = c[fm][fn][q] * INV_T;
                float e = __expf(s);
                rsum[fm][i] += e;
                csum[fn * 2 + j] += e;
                if (diag_cta) {
                    int gr = rowBase + warp_m * 32 + fm * 16 + i * 8 + (lane >> 2);
                    int gc = colBase + warp_n * 64 + fn * 8 + (lane & 3) * 2 + j;
                    if (gr == gc) g_diag[p * BATCH + gr] = s;
                }
            }

#pragma unroll
    for (int fm = 0; fm < 2; fm++)
#pragma unroll
        for (int i = 0; i < 2; i++) {
            float v = rsum[fm][i];
            v += __shfl_xor_sync(0xFFFFFFFFu, v, 1);
            v += __shfl_xor_sync(0xFFFFFFFFu, v, 2);
            if ((lane & 3) == 0) {
                int gr = rowBase + warp_m * 32 + fm * 16 + i * 8 + (lane >> 2);
                atomicAdd(&g_rowsum[p * BATCH + gr], v);
            }
        }

#pragma unroll
    for (int t = 0; t < 16; t++) {
        float v = csum[t];
        v += __shfl_xor_sync(0xFFFFFFFFu, v, 4);
        v += __shfl_xor_sync(0xFFFFFFFFu, v, 8);
        v += __shfl_xor_sync(0xFFFFFFFFu, v, 16);
        if (lane < 4) {
            int fn = t >> 1, j = t & 1;
            int gc = colBase + warp_n * 64 + fn * 8 + lane * 2 + j;
            atomicAdd(&g_colsum[p * BATCH + gc], v);
        }
    }

    // ------------------- fused finalize (last CTA only) --------------------
    __shared__ unsigned int s_last;
    __threadfence();                       // make this CTA's atomics visible
    __syncthreads();
    if (tid == 0) s_last = atomicAdd(&g_ctr, 1u);
    __syncthreads();
    if (s_last == NCTA - 1) {
        float acc = 0.0f;
        for (int idx = tid; idx < NPAIR * BATCH; idx += 256)
            acc += 0.5f * (__logf(g_rowsum[idx]) + __logf(g_colsum[idx]))
                 - g_diag[idx];
#pragma unroll
        for (int o = 16; o > 0; o >>= 1)
            acc += __shfl_xor_sync(0xFFFFFFFFu, acc, o);
        __shared__ float ws[8];
        if (lane == 0) ws[w] = acc;
        __syncthreads();
        if (tid == 0) {
            float s = 0.0f;
#pragma unroll
            for (int i = 0; i < 8; i++) s += ws[i];
            out[0] = s * (1.0f / ((float)BATCH * (float)NPAIR));
        }
    }
}

// ---------------------------------------------------------------------------
extern "C" void kernel_launch(void* const* d_in, const int* in_sizes, int n_in,
                              void* d_out, int out_size) {
    const float* z0 = (const float*)d_in[0];
    const float* z1 = (const float*)d_in[1];
    const float* z2 = (const float*)d_in[2];
    const float* z3 = (const float*)d_in[3];
    float* out = (float*)d_out;
    (void)in_sizes; (void)n_in; (void)out_size;

    cudaFuncSetAttribute(pair_mma_kernel,
                         cudaFuncAttributeMaxDynamicSharedMemorySize, SMEM_TOTAL);

    normalize_kernel<<<(2 * BATCH) / 8, 256>>>(z0, z1, z2, z3, out);
    dim3 ggrid(32, 32, NPAIR);
    pair_mma_kernel<<<ggrid, 256, SMEM_TOTAL>>>(out);
}

// round 16
// speedup vs baseline: 1.5172x; 1.5172x over previous
#include <cuda_runtime.h>
#include <cuda_bf16.h>
#include <math.h>
#include <stdint.h>

#define BATCH 4096
#define DIM   256
#define NPAIR 6
#define INV_T 10.0f

__constant__ int c_pi[NPAIR] = {0, 0, 0, 1, 1, 2};
__constant__ int c_pj[NPAIR] = {1, 2, 3, 2, 3, 3};

// Scratch (allocs forbidden)
__device__ __nv_bfloat16 g_znb[4 * BATCH * DIM];   // normalized views, bf16
__device__ float g_rowsum[NPAIR * BATCH];
__device__ float g_colsum[NPAIR * BATCH];
__device__ float g_diag[NPAIR * BATCH];

// ---------------------------------------------------------------------------
__device__ __forceinline__ uint32_t smem_u32(const void* p) {
    uint32_t a;
    asm("{ .reg .u64 t; cvta.to.shared.u64 t, %1; cvt.u32.u64 %0, t; }"
        : "=r"(a) : "l"(p));
    return a;
}

#define CP_ASYNC16(smem, gptr) \
    asm volatile("cp.async.cg.shared.global [%0], [%1], 16;" \
                 :: "r"(smem), "l"(gptr) : "memory")
#define CP_COMMIT() asm volatile("cp.async.commit_group;" ::: "memory")
#define CP_WAIT(n)  asm volatile("cp.async.wait_group %0;" :: "n"(n) : "memory")

#define LDMATRIX_X4(r0, r1, r2, r3, addr) \
    asm volatile("ldmatrix.sync.aligned.m8n8.x4.shared.b16 {%0,%1,%2,%3}, [%4];" \
                 : "=r"(r0), "=r"(r1), "=r"(r2), "=r"(r3) : "r"(addr))

#define MMA_BF16(c, a, b) \
    asm volatile("mma.sync.aligned.m16n8k16.row.col.f32.bf16.bf16.f32 " \
                 "{%0,%1,%2,%3}, {%4,%5,%6,%7}, {%8,%9}, {%0,%1,%2,%3};" \
                 : "+f"((c)[0]), "+f"((c)[1]), "+f"((c)[2]), "+f"((c)[3]) \
                 : "r"((a)[0]), "r"((a)[1]), "r"((a)[2]), "r"((a)[3]), \
                   "r"((b)[0]), "r"((b)[1]))

// ---------------------------------------------------------------------------
// Kernel 1: zero accumulators (fused) + L2-normalize -> bf16.
// Two rows per warp (MLP 4).
// ---------------------------------------------------------------------------
__global__ void normalize_kernel(const float* __restrict__ z0,
                                 const float* __restrict__ z1,
                                 const float* __restrict__ z2,
                                 const float* __restrict__ z3,
                                 float* __restrict__ out) {
    int gidx = blockIdx.x * blockDim.x + threadIdx.x;
    if (gidx < NPAIR * BATCH) {
        g_rowsum[gidx] = 0.0f;
        g_colsum[gidx] = 0.0f;
    }
    if (gidx == 0) out[0] = 0.0f;

    int gwarp = gidx >> 5;                 // 0 .. 2*BATCH-1
    int lane  = threadIdx.x & 31;
    if (gwarp >= 2 * BATCH) return;

    float4 v[2][2];
    float  ss[2];
    const float* srcs[2];
#pragma unroll
    for (int r = 0; r < 2; r++) {
        int fr   = gwarp * 2 + r;          // flat row 0..16383
        int view = fr >> 12;
        int row  = fr & (BATCH - 1);
        const float* src;
        switch (view) {
            case 0: src = z0; break;
            case 1: src = z1; break;
            case 2: src = z2; break;
            default: src = z3; break;
        }
        srcs[r] = src + (size_t)row * DIM;
    }
#pragma unroll
    for (int r = 0; r < 2; r++) {
        const float4* s4 = (const float4*)srcs[r];
        v[r][0] = s4[lane * 2 + 0];
        v[r][1] = s4[lane * 2 + 1];
    }
#pragma unroll
    for (int r = 0; r < 2; r++) {
        float4 a = v[r][0], b = v[r][1];
        ss[r] = a.x * a.x + a.y * a.y + a.z * a.z + a.w * a.w
              + b.x * b.x + b.y * b.y + b.z * b.z + b.w * b.w;
    }
#pragma unroll
    for (int o = 16; o > 0; o >>= 1) {
        ss[0] += __shfl_xor_sync(0xFFFFFFFFu, ss[0], o);
        ss[1] += __shfl_xor_sync(0xFFFFFFFFu, ss[1], o);
    }
#pragma unroll
    for (int r = 0; r < 2; r++) {
        float inv = 1.0f / fmaxf(sqrtf(ss[r]), 1e-8f);
        float4 a = v[r][0], b = v[r][1];
        __nv_bfloat162 p0 = __floats2bfloat162_rn(a.x * inv, a.y * inv);
        __nv_bfloat162 p1 = __floats2bfloat162_rn(a.z * inv, a.w * inv);
        __nv_bfloat162 p2 = __floats2bfloat162_rn(b.x * inv, b.y * inv);
        __nv_bfloat162 p3 = __floats2bfloat162_rn(b.z * inv, b.w * inv);
        uint4 o4;
        o4.x = reinterpret_cast<uint32_t&>(p0);
        o4.y = reinterpret_cast<uint32_t&>(p1);
        o4.z = reinterpret_cast<uint32_t&>(p2);
        o4.w = reinterpret_cast<uint32_t&>(p3);
        int fr = gwarp * 2 + r;
        uint4* dst = (uint4*)(g_znb + (size_t)fr * DIM);
        dst[lane] = o4;
    }
}

// ---------------------------------------------------------------------------
// Kernel 2: R6-winner bf16 mma.sync pair GEMM (verbatim).
// CTA tile 128x128, 8 warps 4x2, warp tile 32x64. K chunks of 64, 3-stage
// cp.async pipeline, one barrier per chunk.
// SMEM chunk layout (128x64 bf16, 16 KB):
//   element (row, k): byte = row*128 + ((k/8) ^ (row&7))*16 + (k%8)*2
// ---------------------------------------------------------------------------
#define KC 64
#define CHUNK_BYTES (128 * 128)     // 16 KB
#define NSTAGE 3
#define SMEM_TOTAL (2 * NSTAGE * CHUNK_BYTES)   // 96 KB

__device__ __forceinline__ void load_chunk(uint32_t s_base,
                                           const __nv_bfloat16* __restrict__ src,
                                           int kc, int tid) {
#pragma unroll
    for (int it = 0; it < 4; it++) {
        int idx = it * 256 + tid;         // 0..1023
        int row = idx >> 3;
        int c   = idx & 7;
        const __nv_bfloat16* g = src + (size_t)row * DIM + kc * KC + c * 8;
        uint32_t s = s_base + row * 128 + ((c ^ (row & 7)) << 4);
        CP_ASYNC16(s, g);
    }
}

__global__ void __launch_bounds__(256) pair_mma_kernel() {
    extern __shared__ char smraw[];
    uint32_t sbase = smem_u32(smraw);

    int tid = threadIdx.x;
    int w = tid >> 5, lane = tid & 31;
    int warp_m = w & 3;                 // 0..3 -> 32 rows each
    int warp_n = w >> 2;                // 0..1 -> 64 cols each

    int p = blockIdx.z;
    int rowBase = blockIdx.y * 128;
    int colBase = blockIdx.x * 128;
    const __nv_bfloat16* Asrc = g_znb + ((size_t)c_pi[p] * BATCH + rowBase) * DIM;
    const __nv_bfloat16* Bsrc = g_znb + ((size_t)c_pj[p] * BATCH + colBase) * DIM;

    uint32_t sA[NSTAGE], sB[NSTAGE];
#pragma unroll
    for (int s = 0; s < NSTAGE; s++) {
        sA[s] = sbase + s * CHUNK_BYTES;
        sB[s] = sbase + (NSTAGE + s) * CHUNK_BYTES;
    }

    float c[2][8][4];
#pragma unroll
    for (int i = 0; i < 2; i++)
#pragma unroll
        for (int j = 0; j < 8; j++)
#pragma unroll
            for (int q = 0; q < 4; q++) c[i][j][q] = 0.0f;

    int ar = warp_m * 32 + (lane & 15);
    int akg = lane >> 4;
    int bn = warp_n * 64 + ((lane >> 4) << 3) + (lane & 7);
    int bkg = (lane >> 3) & 1;

    load_chunk(sA[0], Asrc, 0, tid);
    load_chunk(sB[0], Bsrc, 0, tid);
    CP_COMMIT();
    load_chunk(sA[1], Asrc, 1, tid);
    load_chunk(sB[1], Bsrc, 1, tid);
    CP_COMMIT();

#pragma unroll
    for (int kc = 0; kc < 4; kc++) {
        if (kc < 3) { CP_WAIT(1); } else { CP_WAIT(0); }
        __syncthreads();
        if (kc < 2) {
            int nb = (kc + 2) % NSTAGE;
            load_chunk(sA[nb], Asrc, kc + 2, tid);
            load_chunk(sB[nb], Bsrc, kc + 2, tid);
            CP_COMMIT();
        }
        int buf = kc % NSTAGE;

#pragma unroll
        for (int kk = 0; kk < 4; kk++) {
            uint32_t a[2][4];
#pragma unroll
            for (int fm = 0; fm < 2; fm++) {
                int r = ar + fm * 16;
                int kg = kk * 2 + akg;
                uint32_t addr = sA[buf] + r * 128 + ((kg ^ (r & 7)) << 4);
                LDMATRIX_X4(a[fm][0], a[fm][1], a[fm][2], a[fm][3], addr);
            }
            uint32_t b[4][4];
#pragma unroll
            for (int nb = 0; nb < 4; nb++) {
                int n = bn + nb * 16;
                int kg = kk * 2 + bkg;
                uint32_t addr = sB[buf] + n * 128 + ((kg ^ (n & 7)) << 4);
                LDMATRIX_X4(b[nb][0], b[nb][1], b[nb][2], b[nb][3], addr);
            }
#pragma unroll
            for (int fm = 0; fm < 2; fm++)
#pragma unroll
                for (int nb = 0; nb < 4; nb++) {
                    uint32_t bf0[2] = {b[nb][0], b[nb][1]};
                    uint32_t bf1[2] = {b[nb][2], b[nb][3]};
                    MMA_BF16(c[fm][nb * 2 + 0], a[fm], bf0);
                    MMA_BF16(c[fm][nb * 2 + 1], a[fm], bf1);
                }
        }
    }

    // ------------------- epilogue (register-only, proven R6 form) ----------
    bool diag_cta = (rowBase == colBase);
    float rsum[2][2] = {{0, 0}, {0, 0}};
    float csum[16];
#pragma unroll
    for (int i = 0; i < 16; i++) csum[i] = 0.0f;

#pragma unroll
    for (int fm = 0; fm < 2; fm++)
#pragma unroll
        for (int fn = 0; fn < 8; fn++)
#pragma unroll
            for (int q = 0; q < 4; q++) {
                int i = q >> 1, j = q & 1;
                float s = c[fm][fn][q] * INV_T;
                float e = __expf(s);
                rsum[fm][i] += e;
                csum[fn * 2 + j] += e;
                if (diag_cta) {
                    int gr = rowBase + warp_m * 32 + fm * 16 + i * 8 + (lane >> 2);
                    int gc = colBase + warp_n * 64 + fn * 8 + (lane & 3) * 2 + j;
                    if (gr == gc) g_diag[p * BATCH + gr] = s;
                }
            }

#pragma unroll
    for (int fm = 0; fm < 2; fm++)
#pragma unroll
        for (int i = 0; i < 2; i++) {
            float v = rsum[fm][i];
            v += __shfl_xor_sync(0xFFFFFFFFu, v, 1);
            v += __shfl_xor_sync(0xFFFFFFFFu, v, 2);
            if ((lane & 3) == 0) {
                int gr = rowBase + warp_m * 32 + fm * 16 + i * 8 + (lane >> 2);
                atomicAdd(&g_rowsum[p * BATCH + gr], v);
            }
        }

#pragma unroll
    for (int t = 0; t < 16; t++) {
        float v = csum[t];
        v += __shfl_xor_sync(0xFFFFFFFFu, v, 4);
        v += __shfl_xor_sync(0xFFFFFFFFu, v, 8);
        v += __shfl_xor_sync(0xFFFFFFFFu, v, 16);
        if (lane < 4) {
            int fn = t >> 1, j = t & 1;
            int gc = colBase + warp_n * 64 + fn * 8 + lane * 2 + j;
            atomicAdd(&g_colsum[p * BATCH + gc], v);
        }
    }
}

// ---------------------------------------------------------------------------
// Kernel 3: per-(pair,b) loss terms + global mean (__logf = MUFU lg2)
// ---------------------------------------------------------------------------
__global__ void finalize_kernel(float* __restrict__ out) {
    int idx = blockIdx.x * 256 + threadIdx.x;
    float v = 0.0f;
    if (idx < NPAIR * BATCH)
        v = 0.5f * (__logf(g_rowsum[idx]) + __logf(g_colsum[idx])) - g_diag[idx];
#pragma unroll
    for (int o = 16; o > 0; o >>= 1)
        v += __shfl_xor_sync(0xFFFFFFFFu, v, o);
    __shared__ float ws[8];
    int w = threadIdx.x >> 5, l = threadIdx.x & 31;
    if (l == 0) ws[w] = v;
    __syncthreads();
    if (threadIdx.x == 0) {
        float s = 0.0f;
#pragma unroll
        for (int i = 0; i < 8; i++) s += ws[i];
        atomicAdd(out, s * (1.0f / ((float)BATCH * (float)NPAIR)));
    }
}

// ---------------------------------------------------------------------------
extern "C" void kernel_launch(void* const* d_in, const int* in_sizes, int n_in,
                              void* d_out, int out_size) {
    const float* z0 = (const float*)d_in[0];
    const float* z1 = (const float*)d_in[1];
    const float* z2 = (const float*)d_in[2];
    const float* z3 = (const float*)d_in[3];
    float* out = (float*)d_out;
    (void)in_sizes; (void)n_in; (void)out_size;

    cudaFuncSetAttribute(pair_mma_kernel,
                         cudaFuncAttributeMaxDynamicSharedMemorySize, SMEM_TOTAL);

    normalize_kernel<<<(2 * BATCH) / 8, 256>>>(z0, z1, z2, z3, out);
    dim3 ggrid(32, 32, NPAIR);
    pair_mma_kernel<<<ggrid, 256, SMEM_TOTAL>>>();
    finalize_kernel<<<(NPAIR * BATCH + 255) / 256, 256>>>(out);
}